// round 9
// baseline (speedup 1.0000x reference)
#include <cuda_runtime.h>
#include <cuda_bf16.h>

#define TPB     128
#define SPLIT   16
#define MAX_B   1024
#define MAX_NT  2048
#define BATCH   16

// cross-kernel scratch (allocation-free). g_key/g_cnt zero at load and
// self-reset by the finisher -> deterministic across graph replays.
__device__ unsigned long long g_key[MAX_B];
__device__ int                g_cnt[MAX_B];
__device__ int                g_list[MAX_B];
__device__ int                g_nrej;

// ---------- Kernel A: token-parallel gather + per-request scan --------------
__global__ void __launch_bounds__(512)
scan_compact(const float* __restrict__ draft_probs,
             const float* __restrict__ target_probs,
             const float* __restrict__ uniform_probs,
             const int*   __restrict__ draft_token_ids,
             const int*   __restrict__ cu,
             const int*   __restrict__ bonus,
             float*       __restrict__ out,
             int B, int NT, int V, int L)
{
    __shared__ int   sid[MAX_NT];
    __shared__ float stp[MAX_NT];
    __shared__ float sdp[MAX_NT];
    __shared__ float su [MAX_NT];
    __shared__ int   scu[MAX_B];
    __shared__ int   wcnt[16];

    const int tid = threadIdx.x;

    // round 1: cu and token ids (independent, concurrent)
    for (int r = tid; r < B; r += 512) scu[r] = __ldg(&cu[r]);
    for (int t = tid; t < NT; t += 512) sid[t] = __ldg(&draft_token_ids[t]);
    __syncthreads();

    // round 2: prob/uniform gathers, token-parallel
    for (int t = tid; t < NT; t += 512) {
        const int idv = sid[t];
        stp[t] = __ldg(&target_probs[(size_t)t * V + idv]);
        sdp[t] = __ldg(&draft_probs [(size_t)t * V + idv]);
        su [t] = __ldg(&uniform_probs[t]);
    }
    __syncthreads();

    // per-request scan (threads 0..B-1), faithful to reference
    const int r      = tid;
    const bool activ = (r < B);
    int start = 0, end = 0;
    if (activ) { start = (r == 0) ? 0 : scu[r - 1]; end = scu[r]; }
    const int nd  = end - start;
    const int lim = (nd < L) ? nd : L;

    float pi = 1.0f, U = 1.0f;
    int last = -1;
    for (int j = 0; j < lim; j++) {
        const int t = start + j;
        const float dpj = sdp[t];
        const float ratio = (dpj > 0.0f) ? (stp[t] / dpj) : 1.0f;
        pi = fminf(pi * ratio, 1.0f);
        U *= su[t];
        if ((dpj > 0.0f) && (pi >= U)) last = j;
    }

    const int rejected  = (activ && nd > 0 && last != nd - 1) ? 1 : 0;
    const int write_col = rejected ? (last + 1) : nd;

    if (activ) {
        float* orow = out + (size_t)r * (L + 1);
        for (int j = 0; j <= L; j++) {
            float v = -1.0f;
            if (j < L && j <= last) v = (float)sid[start + j];
            orow[j] = v;
        }
        if (!rejected) orow[write_col] = (float)__ldg(&bonus[r]);
    }

    int rec = start + last + 1;
    rec = (rec < 0) ? 0 : rec;
    rec = (rec > NT - 1) ? (NT - 1) : rec;

    // compaction (ballot + cross-warp prefix; deterministic order)
    const int warp = tid >> 5, lane = tid & 31;
    const unsigned ball = __ballot_sync(0xffffffffu, rejected);
    const int rank = __popc(ball & ((1u << lane) - 1));
    if (lane == 0) wcnt[warp] = __popc(ball);
    __syncthreads();
    int base = 0, total = 0;
    #pragma unroll
    for (int w = 0; w < 16; w++) {
        if (w < warp) base += wcnt[w];
        total += wcnt[w];
    }
    if (rejected)
        g_list[base + rank] = r | (write_col << 8) | (rec << 12);
    if (tid == 0) g_nrej = total;
}

// ---------- Kernel B: single-round deep-MLP split argmax --------------------
__global__ void __launch_bounds__(TPB)
argmax_kernel(const float* __restrict__ target_probs,
              float* __restrict__ out, int V, int L)
{
    const int row = blockIdx.x / SPLIT;
    if (row >= g_nrej) return;
    const int s   = blockIdx.x % SPLIT;
    const int tid = threadIdx.x;

    const int e   = g_list[row];               // broadcast L2 read
    const int r   = e & 0xff;
    const int pos = (e >> 8) & 0xf;
    const int rec = e >> 12;

    const int chunk = (((V + SPLIT - 1) / SPLIT) + 3) & ~3;   // 4-aligned floats
    const int nact  = (V + chunk - 1) / chunk;
    if (s >= nact) return;
    const int beg = s * chunk;
    const int fin = min(V, beg + chunk);

    const float*  rowp = target_probs + (size_t)rec * V;
    const float4* row4 = reinterpret_cast<const float4*>(rowp);
    const int n4beg = beg >> 2;
    const int n4end = fin >> 2;

    float  best  = -1.0f;                      // probs >= 0
    int    bbase = -1;
    float4 bv    = make_float4(0.f, 0.f, 0.f, 0.f);

    // one front-issued batch of BATCH loads per thread per outer iteration
    for (int i0 = n4beg + tid; i0 < n4end; i0 += BATCH * TPB) {
        float4 v[BATCH];
        #pragma unroll
        for (int k = 0; k < BATCH; k++) {
            const int ik = i0 + k * TPB;
            const int safe = (ik < n4end) ? ik : i0;          // i0 always valid
            v[k] = __ldg(&row4[safe]);
        }
        #pragma unroll
        for (int k = 0; k < BATCH; k++) {
            const int ik = i0 + k * TPB;
            const float m = fmaxf(fmaxf(v[k].x, v[k].y), fmaxf(v[k].z, v[k].w));
            if ((ik < n4end) && (m > best)) {
                best = m; bbase = ik << 2; bv = v[k];
            }
        }
    }

    int bidx = 0x7fffffff;
    if (bbase >= 0) {
        bidx = bbase + ((bv.x == best) ? 0 : (bv.y == best) ? 1
                      : (bv.z == best) ? 2 : 3);
    }
    // scalar tail (V not divisible by 4)
    {
        const int t0 = n4end << 2;
        if (tid < fin - t0) {
            const float vv = __ldg(&rowp[t0 + tid]);
            const int   ii = t0 + tid;
            if (vv > best || (vv == best && ii < bidx)) { best = vv; bidx = ii; }
        }
    }

    // warp reduce (min-index tie-break -> global first occurrence)
    #pragma unroll
    for (int off = 16; off > 0; off >>= 1) {
        const float ov = __shfl_down_sync(0xffffffffu, best, off);
        const int   oi = __shfl_down_sync(0xffffffffu, bidx, off);
        if (ov > best || (ov == best && oi < bidx)) { best = ov; bidx = oi; }
    }

    __shared__ float wv[TPB / 32];
    __shared__ int   wi[TPB / 32];
    const int warp = tid >> 5, lane = tid & 31;
    if (lane == 0) { wv[warp] = best; wi[warp] = bidx; }
    __syncthreads();

    if (tid == 0) {
        #pragma unroll
        for (int w = 1; w < TPB / 32; w++) {
            if (wv[w] > best || (wv[w] == best && wi[w] < bidx)) {
                best = wv[w]; bidx = wi[w];
            }
        }
        // pack: prob bits (monotone for >=0 floats) | ~index (ties -> min idx)
        const unsigned long long key =
            ((unsigned long long)__float_as_uint(best) << 32) |
            (unsigned long long)(~(unsigned)bidx);
        atomicMax(&g_key[r], key);
        __threadfence();
        const int old = atomicAdd(&g_cnt[r], 1);
        if (old == nact - 1) {                       // last finisher
            const unsigned long long k = atomicMax(&g_key[r], 0ULL);
            const int idx = (int)(~(unsigned)(k & 0xffffffffULL));
            out[(size_t)r * (L + 1) + pos] = (float)idx;
            g_key[r] = 0ULL;                         // self-reset for replay
            g_cnt[r] = 0;
        }
    }
}

extern "C" void kernel_launch(void* const* d_in, const int* in_sizes, int n_in,
                              void* d_out, int out_size) {
    const float* draft_probs     = (const float*)d_in[0];
    const float* target_probs    = (const float*)d_in[1];
    const float* uniform_probs   = (const float*)d_in[2];
    const int*   draft_token_ids = (const int*)  d_in[3];
    const int*   cu              = (const int*)  d_in[4];
    const int*   bonus           = (const int*)  d_in[5];
    float*       out             = (float*)d_out;

    const int NT = in_sizes[3];
    const int B  = in_sizes[4];
    const int V  = in_sizes[0] / NT;
    const int L  = out_size / B - 1;

    scan_compact<<<1, 512>>>(draft_probs, target_probs, uniform_probs,
                             draft_token_ids, cu, bonus, out, B, NT, V, L);
    argmax_kernel<<<B * SPLIT, TPB>>>(target_probs, out, V, L);
}

// round 10
// speedup vs baseline: 1.3145x; 1.3145x over previous
#include <cuda_runtime.h>
#include <cuda_bf16.h>

#define TPB     256
#define SPLIT   8
#define MAX_B   1024
#define MAX_LL  8
#define BATCH   8

// cross-block scratch (allocation-free). Zero at load; self-reset each replay.
__device__ unsigned long long g_key[MAX_B];
__device__ int                g_cnt[MAX_B];
__device__ int                g_list[MAX_B];
__device__ int                g_nrej;
__device__ int                g_flag;
__device__ int                g_done;

__global__ void __launch_bounds__(TPB)
fused_spin_kernel(const float* __restrict__ draft_probs,
                  const float* __restrict__ target_probs,
                  const float* __restrict__ uniform_probs,
                  const int*   __restrict__ draft_token_ids,
                  const int*   __restrict__ cu,
                  const int*   __restrict__ bonus,
                  float*       __restrict__ out,
                  int B, int NT, int V, int L)
{
    const int bid = blockIdx.x;
    const int tid = threadIdx.x;

    if (bid == 0) {
        // ================= scan + compaction (producer block) ================
        const bool activ = (tid < B);
        int start = 0, end = 0;
        if (activ) {
            start = (tid == 0) ? 0 : __ldg(&cu[tid - 1]);
            end   = __ldg(&cu[tid]);
        }
        const int nd  = end - start;
        const int lim = (nd < L) ? nd : L;

        // batched independent gathers: ids first, then probs/uniform
        int   id[MAX_LL];
        float tp[MAX_LL], dp[MAX_LL], uu[MAX_LL];
        #pragma unroll
        for (int j = 0; j < MAX_LL; j++) {
            id[j] = 0;
            if (j < lim) id[j] = __ldg(&draft_token_ids[start + j]);
        }
        #pragma unroll
        for (int j = 0; j < MAX_LL; j++) {
            tp[j] = 0.f; dp[j] = 0.f; uu[j] = 1.f;
            if (j < lim) {
                const int idx = start + j;
                tp[j] = __ldg(&target_probs[(size_t)idx * V + id[j]]);
                dp[j] = __ldg(&draft_probs [(size_t)idx * V + id[j]]);
                uu[j] = __ldg(&uniform_probs[idx]);
            }
        }

        // faithful reference scan
        float pi = 1.0f, U = 1.0f;
        int last = -1;
        #pragma unroll
        for (int j = 0; j < MAX_LL; j++) {
            if (j >= lim) break;
            const float ratio = (dp[j] > 0.0f) ? (tp[j] / dp[j]) : 1.0f;
            pi = fminf(pi * ratio, 1.0f);
            U *= uu[j];
            if ((dp[j] > 0.0f) && (pi >= U)) last = j;
        }

        const int rejected  = (activ && nd > 0 && last != nd - 1) ? 1 : 0;
        const int write_col = rejected ? (last + 1) : nd;

        int rec = start + last + 1;
        rec = (rec < 0) ? 0 : rec;
        rec = (rec > NT - 1) ? (NT - 1) : rec;

        // compaction: ballot + cross-warp prefix (deterministic)
        __shared__ int wcnt[TPB / 32];
        const int warp = tid >> 5, lane = tid & 31;
        const unsigned ball = __ballot_sync(0xffffffffu, rejected);
        const int rank = __popc(ball & ((1u << lane) - 1));
        if (lane == 0) wcnt[warp] = __popc(ball);
        __syncthreads();
        int base = 0, total = 0;
        #pragma unroll
        for (int w = 0; w < TPB / 32; w++) {
            if (w < warp) base += wcnt[w];
            total += wcnt[w];
        }
        if (rejected)
            g_list[base + rank] = tid | (write_col << 8) | (rec << 12);
        if (tid == 0) g_nrej = total;

        // publish: every thread fences its own stores, then thread0 raises flag
        __threadfence();
        __syncthreads();
        if (tid == 0) atomicExch(&g_flag, 1);

        // output rows (independent of consumers' argmax)
        if (activ) {
            float* orow = out + (size_t)tid * (L + 1);
            #pragma unroll
            for (int j = 0; j < MAX_LL + 1; j++) {
                if (j > L) break;
                float v = -1.0f;
                if (j < L && j <= last) v = (float)id[j];
                orow[j] = v;
            }
            if (!rejected) orow[write_col] = (float)__ldg(&bonus[tid]);
        }
    } else {
        // ================= consumers: spin until scan published ==============
        if (tid == 0) {
            volatile int* f = &g_flag;
            while (*f == 0) __nanosleep(64);
            __threadfence();        // acquire: order g_list/g_nrej reads after
        }
        __syncthreads();
    }

    // ======================= split argmax over rejected rows =================
    const int nrej = g_nrej;
    const int row  = bid / SPLIT;
    const int s    = bid % SPLIT;

    if (row < nrej) {
        const int e   = g_list[row];            // broadcast L2 read
        const int r   = e & 0xff;
        const int pos = (e >> 8) & 0xf;
        const int rec = e >> 12;

        const int chunk = (((V + SPLIT - 1) / SPLIT) + 3) & ~3;   // 4-aligned
        const int nact  = (V + chunk - 1) / chunk;
        if (s < nact) {
            const int beg = s * chunk;
            const int fin = min(V, beg + chunk);

            const float*  rowp = target_probs + (size_t)rec * V;
            const float4* row4 = reinterpret_cast<const float4*>(rowp);
            const int n4beg = beg >> 2;
            const int n4end = fin >> 2;

            float  best  = -1.0f;               // probs >= 0
            int    bbase = -1;
            float4 bv    = make_float4(0.f, 0.f, 0.f, 0.f);

            for (int i0 = n4beg + tid; i0 < n4end; i0 += BATCH * TPB) {
                float4 v[BATCH];
                #pragma unroll
                for (int k = 0; k < BATCH; k++) {
                    const int ik = i0 + k * TPB;
                    const int safe = (ik < n4end) ? ik : i0;   // i0 always valid
                    v[k] = __ldg(&row4[safe]);
                }
                #pragma unroll
                for (int k = 0; k < BATCH; k++) {
                    const int ik = i0 + k * TPB;
                    const float m = fmaxf(fmaxf(v[k].x, v[k].y),
                                          fmaxf(v[k].z, v[k].w));
                    if ((ik < n4end) && (m > best)) {
                        best = m; bbase = ik << 2; bv = v[k];
                    }
                }
            }

            int bidx = 0x7fffffff;
            if (bbase >= 0) {
                bidx = bbase + ((bv.x == best) ? 0 : (bv.y == best) ? 1
                              : (bv.z == best) ? 2 : 3);
            }
            // scalar tail (V not divisible by 4)
            {
                const int t0 = n4end << 2;
                if (tid < fin - t0) {
                    const float vv = __ldg(&rowp[t0 + tid]);
                    const int   ii = t0 + tid;
                    if (vv > best || (vv == best && ii < bidx)) {
                        best = vv; bidx = ii;
                    }
                }
            }

            // warp reduce (min-index tie-break -> first occurrence)
            #pragma unroll
            for (int off = 16; off > 0; off >>= 1) {
                const float ov = __shfl_down_sync(0xffffffffu, best, off);
                const int   oi = __shfl_down_sync(0xffffffffu, bidx, off);
                if (ov > best || (ov == best && oi < bidx)) {
                    best = ov; bidx = oi;
                }
            }

            __shared__ float wv[TPB / 32];
            __shared__ int   wi[TPB / 32];
            const int warp = tid >> 5, lane = tid & 31;
            if (lane == 0) { wv[warp] = best; wi[warp] = bidx; }
            __syncthreads();

            if (tid == 0) {
                #pragma unroll
                for (int w = 1; w < TPB / 32; w++) {
                    if (wv[w] > best || (wv[w] == best && wi[w] < bidx)) {
                        best = wv[w]; bidx = wi[w];
                    }
                }
                // pack: prob bits (monotone >=0) | ~index (ties -> min index)
                const unsigned long long key =
                    ((unsigned long long)__float_as_uint(best) << 32) |
                    (unsigned long long)(~(unsigned)bidx);
                atomicMax(&g_key[r], key);
                __threadfence();
                const int old = atomicAdd(&g_cnt[r], 1);
                if (old == nact - 1) {          // row finisher
                    const unsigned long long k = atomicMax(&g_key[r], 0ULL);
                    const int idx = (int)(~(unsigned)(k & 0xffffffffULL));
                    out[(size_t)r * (L + 1) + pos] = (float)idx;
                    g_key[r] = 0ULL;            // self-reset for next replay
                    g_cnt[r] = 0;
                }
            }
        }
    }

    // ==================== global finisher resets the flag ====================
    if (tid == 0) {
        __threadfence();
        const int d = atomicAdd(&g_done, 1);
        if (d == (int)gridDim.x - 1) {
            g_flag = 0;
            g_done = 0;
        }
    }
}

extern "C" void kernel_launch(void* const* d_in, const int* in_sizes, int n_in,
                              void* d_out, int out_size) {
    const float* draft_probs     = (const float*)d_in[0];
    const float* target_probs    = (const float*)d_in[1];
    const float* uniform_probs   = (const float*)d_in[2];
    const int*   draft_token_ids = (const int*)  d_in[3];
    const int*   cu              = (const int*)  d_in[4];
    const int*   bonus           = (const int*)  d_in[5];
    float*       out             = (float*)d_out;

    const int NT = in_sizes[3];
    const int B  = in_sizes[4];
    const int V  = in_sizes[0] / NT;
    const int L  = out_size / B - 1;

    fused_spin_kernel<<<B * SPLIT, TPB>>>(draft_probs, target_probs,
                                          uniform_probs, draft_token_ids,
                                          cu, bonus, out, B, NT, V, L);
}

// round 11
// speedup vs baseline: 1.3375x; 1.0175x over previous
#include <cuda_runtime.h>
#include <cuda_bf16.h>

#define TPB     256
#define SPLIT   8
#define MAX_B   1024
#define MAX_NT  2048
#define BATCH   8

// cross-kernel scratch (allocation-free). g_key/g_cnt zero at load and
// self-reset by the finisher -> deterministic across graph replays.
__device__ unsigned long long g_key[MAX_B];
__device__ int                g_cnt[MAX_B];
__device__ int                g_list[MAX_B];
__device__ int                g_nrej;

// ---------- Kernel A: token-parallel gather + per-request scan --------------
__global__ void __launch_bounds__(512)
scan_compact(const float* __restrict__ draft_probs,
             const float* __restrict__ target_probs,
             const float* __restrict__ uniform_probs,
             const int*   __restrict__ draft_token_ids,
             const int*   __restrict__ cu,
             const int*   __restrict__ bonus,
             float*       __restrict__ out,
             int B, int NT, int V, int L)
{
    __shared__ int   sid[MAX_NT];
    __shared__ float stp[MAX_NT];
    __shared__ float sdp[MAX_NT];
    __shared__ float su [MAX_NT];
    __shared__ int   scu[MAX_B];
    __shared__ int   wcnt[16];

    const int tid = threadIdx.x;

    // round 1: cu and token ids (independent, concurrent)
    for (int r = tid; r < B; r += 512) scu[r] = __ldg(&cu[r]);
    for (int t = tid; t < NT; t += 512) sid[t] = __ldg(&draft_token_ids[t]);
    __syncthreads();

    // round 2: prob/uniform gathers, token-parallel (one latency round)
    for (int t = tid; t < NT; t += 512) {
        const int idv = sid[t];
        stp[t] = __ldg(&target_probs[(size_t)t * V + idv]);
        sdp[t] = __ldg(&draft_probs [(size_t)t * V + idv]);
        su [t] = __ldg(&uniform_probs[t]);
    }
    __syncthreads();

    // per-request scan (threads 0..B-1), faithful to reference
    const int r      = tid;
    const bool activ = (r < B);
    int start = 0, end = 0;
    if (activ) { start = (r == 0) ? 0 : scu[r - 1]; end = scu[r]; }
    const int nd  = end - start;
    const int lim = (nd < L) ? nd : L;

    float pi = 1.0f, U = 1.0f;
    int last = -1;
    for (int j = 0; j < lim; j++) {
        const int t = start + j;
        const float dpj = sdp[t];
        const float ratio = (dpj > 0.0f) ? (stp[t] / dpj) : 1.0f;
        pi = fminf(pi * ratio, 1.0f);
        U *= su[t];
        if ((dpj > 0.0f) && (pi >= U)) last = j;
    }

    const int rejected  = (activ && nd > 0 && last != nd - 1) ? 1 : 0;
    const int write_col = rejected ? (last + 1) : nd;

    int rec = start + last + 1;
    rec = (rec < 0) ? 0 : rec;
    rec = (rec > NT - 1) ? (NT - 1) : rec;

    // compaction (ballot + cross-warp prefix; deterministic order)
    const int warp = tid >> 5, lane = tid & 31;
    const unsigned ball = __ballot_sync(0xffffffffu, rejected);
    const int rank = __popc(ball & ((1u << lane) - 1));
    if (lane == 0) wcnt[warp] = __popc(ball);
    __syncthreads();
    int base = 0, total = 0;
    #pragma unroll
    for (int w = 0; w < 16; w++) {
        if (w < warp) base += wcnt[w];
        total += wcnt[w];
    }
    if (rejected)
        g_list[base + rank] = r | (write_col << 8) | (rec << 12);
    if (tid == 0) g_nrej = total;

    // publish to the dependent grid, then release it as early as possible
    __threadfence();
    __syncthreads();
#if __CUDA_ARCH__ >= 900
    cudaTriggerProgrammaticLaunchCompletion();
#endif

    // output rows (disjoint from kernel B's writes: for rejected rows we skip
    // the recovered-token cell, which B's finisher owns)
    if (activ) {
        float* orow = out + (size_t)r * (L + 1);
        for (int j = 0; j <= L; j++) {
            if (rejected && j == write_col) continue;   // B owns this cell
            float v = -1.0f;
            if (j < L && j <= last) v = (float)sid[start + j];
            orow[j] = v;
        }
        if (!rejected) orow[write_col] = (float)__ldg(&bonus[r]);
    }
}

// ---------- Kernel B (PDL dependent): split argmax over rejected rows -------
__global__ void __launch_bounds__(TPB)
argmax_kernel(const float* __restrict__ target_probs,
              float* __restrict__ out, int V, int L)
{
#if __CUDA_ARCH__ >= 900
    cudaGridDependencySynchronize();   // wait for scan_compact's trigger
#endif

    const int row = blockIdx.x / SPLIT;
    if (row >= g_nrej) return;
    const int s   = blockIdx.x % SPLIT;
    const int tid = threadIdx.x;

    const int e   = g_list[row];               // broadcast L2 read
    const int r   = e & 0xff;
    const int pos = (e >> 8) & 0xf;
    const int rec = e >> 12;

    const int chunk = (((V + SPLIT - 1) / SPLIT) + 3) & ~3;   // 4-aligned
    const int nact  = (V + chunk - 1) / chunk;
    if (s >= nact) return;
    const int beg = s * chunk;
    const int fin = min(V, beg + chunk);

    const float*  rowp = target_probs + (size_t)rec * V;
    const float4* row4 = reinterpret_cast<const float4*>(rowp);
    const int n4beg = beg >> 2;
    const int n4end = fin >> 2;

    float  best  = -1.0f;                      // probs >= 0
    int    bbase = -1;
    float4 bv    = make_float4(0.f, 0.f, 0.f, 0.f);

    for (int i0 = n4beg + tid; i0 < n4end; i0 += BATCH * TPB) {
        float4 v[BATCH];
        #pragma unroll
        for (int k = 0; k < BATCH; k++) {
            const int ik = i0 + k * TPB;
            const int safe = (ik < n4end) ? ik : i0;          // i0 always valid
            v[k] = __ldg(&row4[safe]);
        }
        #pragma unroll
        for (int k = 0; k < BATCH; k++) {
            const int ik = i0 + k * TPB;
            const float m = fmaxf(fmaxf(v[k].x, v[k].y), fmaxf(v[k].z, v[k].w));
            if ((ik < n4end) && (m > best)) {
                best = m; bbase = ik << 2; bv = v[k];
            }
        }
    }

    int bidx = 0x7fffffff;
    if (bbase >= 0) {
        bidx = bbase + ((bv.x == best) ? 0 : (bv.y == best) ? 1
                      : (bv.z == best) ? 2 : 3);
    }
    // scalar tail (V not divisible by 4)
    {
        const int t0 = n4end << 2;
        if (tid < fin - t0) {
            const float vv = __ldg(&rowp[t0 + tid]);
            const int   ii = t0 + tid;
            if (vv > best || (vv == best && ii < bidx)) { best = vv; bidx = ii; }
        }
    }

    // warp reduce (min-index tie-break -> global first occurrence)
    #pragma unroll
    for (int off = 16; off > 0; off >>= 1) {
        const float ov = __shfl_down_sync(0xffffffffu, best, off);
        const int   oi = __shfl_down_sync(0xffffffffu, bidx, off);
        if (ov > best || (ov == best && oi < bidx)) { best = ov; bidx = oi; }
    }

    __shared__ float wv[TPB / 32];
    __shared__ int   wi[TPB / 32];
    const int warp = tid >> 5, lane = tid & 31;
    if (lane == 0) { wv[warp] = best; wi[warp] = bidx; }
    __syncthreads();

    if (tid == 0) {
        #pragma unroll
        for (int w = 1; w < TPB / 32; w++) {
            if (wv[w] > best || (wv[w] == best && wi[w] < bidx)) {
                best = wv[w]; bidx = wi[w];
            }
        }
        // pack: prob bits (monotone for >=0 floats) | ~index (ties -> min idx)
        const unsigned long long key =
            ((unsigned long long)__float_as_uint(best) << 32) |
            (unsigned long long)(~(unsigned)bidx);
        atomicMax(&g_key[r], key);
        __threadfence();
        const int old = atomicAdd(&g_cnt[r], 1);
        if (old == nact - 1) {                       // last finisher
            const unsigned long long k = atomicMax(&g_key[r], 0ULL);
            const int idx = (int)(~(unsigned)(k & 0xffffffffULL));
            out[(size_t)r * (L + 1) + pos] = (float)idx;
            g_key[r] = 0ULL;                         // self-reset for replay
            g_cnt[r] = 0;
        }
    }
}

extern "C" void kernel_launch(void* const* d_in, const int* in_sizes, int n_in,
                              void* d_out, int out_size) {
    const float* draft_probs     = (const float*)d_in[0];
    const float* target_probs    = (const float*)d_in[1];
    const float* uniform_probs   = (const float*)d_in[2];
    const int*   draft_token_ids = (const int*)  d_in[3];
    const int*   cu              = (const int*)  d_in[4];
    const int*   bonus           = (const int*)  d_in[5];
    float*       out             = (float*)d_out;

    const int NT = in_sizes[3];
    const int B  = in_sizes[4];
    const int V  = in_sizes[0] / NT;
    const int L  = out_size / B - 1;

    scan_compact<<<1, 512>>>(draft_probs, target_probs, uniform_probs,
                             draft_token_ids, cu, bonus, out, B, NT, V, L);

    // kernel B with programmatic dependent launch: overlaps its scheduling &
    // prologue with kernel A; blocks wait at cudaGridDependencySynchronize().
    cudaLaunchConfig_t cfg = {};
    cfg.gridDim  = dim3(B * SPLIT, 1, 1);
    cfg.blockDim = dim3(TPB, 1, 1);
    cfg.dynamicSmemBytes = 0;
    cfg.stream = 0;
    cudaLaunchAttribute attrs[1];
    attrs[0].id = cudaLaunchAttributeProgrammaticStreamSerialization;
    attrs[0].val.programmaticStreamSerializationAllowed = 1;
    cfg.attrs = attrs;
    cfg.numAttrs = 1;
    cudaLaunchKernelEx(&cfg, argmax_kernel, target_probs, out, V, L);
}